// round 7
// baseline (speedup 1.0000x reference)
#include <cuda_runtime.h>

// Problem constants (B,H,S,DK) = (4,16,2048,128)
#define Bc   4
#define Hc   16
#define Sc   2048
#define Dc   128
#define BHc  (Bc*Hc)
#define BM   64
#define BN   64
#define SCALE 0.08838834764831845f   // 1/sqrt(128)

// Per-row softmax stats scratch (allocation-free: __device__ globals)
__device__ float g_m[BHc * Sc];
__device__ float g_l[BHc * Sc];

typedef unsigned long long u64;

__device__ __forceinline__ u64 pk2(float lo, float hi) {
    u64 r; asm("mov.b64 %0, {%1, %2};" : "=l"(r) : "f"(lo), "f"(hi)); return r;
}
__device__ __forceinline__ u64 dup2(float x) { return pk2(x, x); }
__device__ __forceinline__ void upk2(u64 v, float& lo, float& hi) {
    asm("mov.b64 {%0, %1}, %2;" : "=f"(lo), "=f"(hi) : "l"(v));
}
__device__ __forceinline__ u64 fma2(u64 a, u64 b, u64 c) {
    u64 d; asm("fma.rn.f32x2 %0, %1, %2, %3;" : "=l"(d) : "l"(a), "l"(b), "l"(c)); return d;
}
__device__ __forceinline__ u64 mul2(u64 a, u64 b) {
    u64 d; asm("mul.rn.f32x2 %0, %1, %2;" : "=l"(d) : "l"(a), "l"(b)); return d;
}

// Dynamic smem layout (floats):
//  Qs: [128][64]  (transposed: [d][row])        8192
//  Ks: [128][64]  (transposed: [d][col])        8192
//  Vs: [64][128]  ([j][d], row-major)           8192
//  Ps: [64][68]   ([row][j], padded)            4352
#define SMEM_FLOATS (8192 + 8192 + 8192 + 64*68)
#define SMEM_BYTES  (SMEM_FLOATS * 4)

__global__ __launch_bounds__(256, 2)
void attn_fwd(const float* __restrict__ q,
              const float* __restrict__ k,
              const float* __restrict__ v,
              float* __restrict__ out,
              float* __restrict__ attn)
{
    extern __shared__ float sm[];
    float* Qs = sm;                 // 128 x 64
    float* Ks = sm + 8192;          // 128 x 64
    float* Vs = sm + 16384;         // 64 x 128
    float* Ps = sm + 24576;         // 64 x 68

    const int tid = threadIdx.x;
    const int tx  = tid & 15;       // column group (4 cols each)
    const int ty  = tid >> 4;       // row group (4 rows each)
    const int ty4 = ty * 4;
    const int tx4 = tx * 4;
    const int bh  = blockIdx.y;
    const int qt  = (gridDim.x - 1) - blockIdx.x;   // heavy tiles scheduled first
    const int i0  = qt * BM;
    const size_t qkv_bh = (size_t)bh * Sc * Dc;

    // ---- Load Q tile transposed (Qs[d][row]); conflict-free smem stores ----
    for (int t = tid; t < BM * 32; t += 256) {
        int row = t & 63;
        int d4  = t >> 6;
        float4 val = *(const float4*)(q + qkv_bh + (size_t)(i0 + row) * Dc + d4 * 4);
        Qs[(d4*4 + 0) * 64 + row] = val.x;
        Qs[(d4*4 + 1) * 64 + row] = val.y;
        Qs[(d4*4 + 2) * 64 + row] = val.z;
        Qs[(d4*4 + 3) * 64 + row] = val.w;
    }
    __syncthreads();

    float m[4] = {-1e30f, -1e30f, -1e30f, -1e30f};
    float l[4] = {0.f, 0.f, 0.f, 0.f};
    u64 O2[8][2];                   // O2[co][p]: packed rows (2p,2p+1), col = tx*8+co
    #pragma unroll
    for (int co = 0; co < 8; co++) { O2[co][0] = 0ull; O2[co][1] = 0ull; }

    for (int jt = 0; jt <= qt; jt++) {
        const int j0 = jt * BN;

        // ---- Load K tile transposed + V tile straight ----
        for (int t = tid; t < BN * 32; t += 256) {
            int row = t & 63;
            int d4  = t >> 6;
            float4 val = *(const float4*)(k + qkv_bh + (size_t)(j0 + row) * Dc + d4 * 4);
            Ks[(d4*4 + 0) * 64 + row] = val.x;
            Ks[(d4*4 + 1) * 64 + row] = val.y;
            Ks[(d4*4 + 2) * 64 + row] = val.z;
            Ks[(d4*4 + 3) * 64 + row] = val.w;
        }
        for (int t = tid; t < BN * 32; t += 256) {
            int row = t >> 5;
            int d4  = t & 31;
            *(float4*)(Vs + row * 128 + d4 * 4) =
                *(const float4*)(v + qkv_bh + (size_t)(j0 + row) * Dc + d4 * 4);
        }
        __syncthreads();

        // ---- S = Q @ K^T (64x64x128), f32x2-packed accumulators ----
        u64 acc[4][2];
        #pragma unroll
        for (int c = 0; c < 4; c++) { acc[c][0] = 0ull; acc[c][1] = 0ull; }

        #pragma unroll 8
        for (int kk = 0; kk < 128; kk++) {
            ulonglong2 a = *(const ulonglong2*)(Qs + kk * 64 + ty4); // rows (0,1),(2,3)
            float4 bv = *(const float4*)(Ks + kk * 64 + tx4);
            float bb[4] = {bv.x, bv.y, bv.z, bv.w};
            #pragma unroll
            for (int c = 0; c < 4; c++) {
                u64 b = dup2(bb[c]);
                acc[c][0] = fma2(a.x, b, acc[c][0]);
                acc[c][1] = fma2(a.y, b, acc[c][1]);
            }
        }

        float s[4][4];  // s[c][r]
        #pragma unroll
        for (int c = 0; c < 4; c++) {
            float r0, r1, r2, r3;
            upk2(acc[c][0], r0, r1);
            upk2(acc[c][1], r2, r3);
            s[c][0] = r0 * SCALE; s[c][1] = r1 * SCALE;
            s[c][2] = r2 * SCALE; s[c][3] = r3 * SCALE;
        }

        // ---- causal mask on the diagonal tile ----
        if (jt == qt) {
            #pragma unroll
            for (int c = 0; c < 4; c++) {
                int j = j0 + tx4 + c;
                #pragma unroll
                for (int r = 0; r < 4; r++) {
                    int i = i0 + ty4 + r;
                    if (j > i) s[c][r] = -1e30f;
                }
            }
        }

        // ---- write RAW scaled scores into attn buffer (scratch for pass 2) ----
        #pragma unroll
        for (int r = 0; r < 4; r++) {
            *(float4*)(attn + ((size_t)bh * Sc + (size_t)(i0 + ty4 + r)) * Sc + j0 + tx4)
                = make_float4(s[0][r], s[1][r], s[2][r], s[3][r]);
        }

        // ---- online softmax (per row, 16-lane butterfly within warp halves) ----
        float corr[4];
        #pragma unroll
        for (int r = 0; r < 4; r++) {
            float tmax = fmaxf(fmaxf(s[0][r], s[1][r]), fmaxf(s[2][r], s[3][r]));
            #pragma unroll
            for (int off = 1; off < 16; off <<= 1)
                tmax = fmaxf(tmax, __shfl_xor_sync(0xffffffffu, tmax, off));
            float nm = fmaxf(m[r], tmax);
            corr[r]  = __expf(m[r] - nm);
            m[r]     = nm;
            float p0 = __expf(s[0][r] - nm);
            float p1 = __expf(s[1][r] - nm);
            float p2 = __expf(s[2][r] - nm);
            float p3 = __expf(s[3][r] - nm);
            float rs = (p0 + p1) + (p2 + p3);
            #pragma unroll
            for (int off = 1; off < 16; off <<= 1)
                rs += __shfl_xor_sync(0xffffffffu, rs, off);
            l[r] = l[r] * corr[r] + rs;
            *(float4*)(Ps + (ty4 + r) * 68 + tx4) = make_float4(p0, p1, p2, p3);
        }

        // ---- rescale O accumulator ----
        {
            u64 c01 = pk2(corr[0], corr[1]);
            u64 c23 = pk2(corr[2], corr[3]);
            #pragma unroll
            for (int co = 0; co < 8; co++) {
                O2[co][0] = mul2(O2[co][0], c01);
                O2[co][1] = mul2(O2[co][1], c23);
            }
        }
        __syncthreads();   // Ps complete before PV reads it

        // ---- O += P @ V (64x128x64) ----
        #pragma unroll 4
        for (int j = 0; j < 64; j++) {
            float a0 = Ps[(ty4 + 0) * 68 + j];
            float a1 = Ps[(ty4 + 1) * 68 + j];
            float a2 = Ps[(ty4 + 2) * 68 + j];
            float a3 = Ps[(ty4 + 3) * 68 + j];
            u64 a01 = pk2(a0, a1);
            u64 a23 = pk2(a2, a3);
            float4 v0 = *(const float4*)(Vs + j * 128 + tx * 8);
            float4 v1 = *(const float4*)(Vs + j * 128 + tx * 8 + 4);
            float bvals[8] = {v0.x, v0.y, v0.z, v0.w, v1.x, v1.y, v1.z, v1.w};
            #pragma unroll
            for (int co = 0; co < 8; co++) {
                u64 b = dup2(bvals[co]);
                O2[co][0] = fma2(a01, b, O2[co][0]);
                O2[co][1] = fma2(a23, b, O2[co][1]);
            }
        }
        __syncthreads();   // safe to overwrite Ks/Vs/Ps next iteration
    }

    // ---- epilogue: O / l, store m & l ----
    float invl[4];
    #pragma unroll
    for (int r = 0; r < 4; r++) invl[r] = 1.0f / l[r];

    float o[8][4];
    #pragma unroll
    for (int co = 0; co < 8; co++) {
        upk2(O2[co][0], o[co][0], o[co][1]);
        upk2(O2[co][1], o[co][2], o[co][3]);
    }
    #pragma unroll
    for (int r = 0; r < 4; r++) {
        float4 w0 = make_float4(o[0][r]*invl[r], o[1][r]*invl[r],
                                o[2][r]*invl[r], o[3][r]*invl[r]);
        float4 w1 = make_float4(o[4][r]*invl[r], o[5][r]*invl[r],
                                o[6][r]*invl[r], o[7][r]*invl[r]);
        size_t ob = qkv_bh + (size_t)(i0 + ty4 + r) * Dc + tx * 8;
        *(float4*)(out + ob)     = w0;
        *(float4*)(out + ob + 4) = w1;
    }
    if (tx == 0) {
        #pragma unroll
        for (int r = 0; r < 4; r++) {
            int row = bh * Sc + i0 + ty4 + r;
            g_m[row] = m[r];
            g_l[row] = l[r];
        }
    }
}

// Pass 2: finalize attn in place: p = exp(s - m)/l for j<=i, 0 otherwise.
__global__ __launch_bounds__(256)
void softmax_fin(float* __restrict__ attn)
{
    const int row = blockIdx.x;          // bh*S + i
    const int i   = row & (Sc - 1);
    const float mm  = g_m[row];
    const float inv = 1.0f / g_l[row];
    float* rp = attn + (size_t)row * Sc;

    for (int c4 = threadIdx.x; c4 < Sc / 4; c4 += blockDim.x) {
        int j0 = c4 << 2;
        float4 o;
        if (j0 + 3 <= i) {
            float4 sv = *(const float4*)(rp + j0);
            o.x = __expf(sv.x - mm) * inv;
            o.y = __expf(sv.y - mm) * inv;
            o.z = __expf(sv.z - mm) * inv;
            o.w = __expf(sv.w - mm) * inv;
        } else if (j0 > i) {
            o = make_float4(0.f, 0.f, 0.f, 0.f);
        } else {
            float t[4];
            #pragma unroll
            for (int u = 0; u < 4; u++) {
                int j = j0 + u;
                t[u] = (j <= i) ? __expf(rp[j] - mm) * inv : 0.f;
            }
            o = make_float4(t[0], t[1], t[2], t[3]);
        }
        *(float4*)(rp + j0) = o;
    }
}

extern "C" void kernel_launch(void* const* d_in, const int* in_sizes, int n_in,
                              void* d_out, int out_size)
{
    const float* q = (const float*)d_in[0];
    const float* k = (const float*)d_in[1];
    const float* v = (const float*)d_in[2];
    // d_in[3] is the causal mask; causality is applied analytically (j<=i).

    float* out  = (float*)d_out;
    float* attn = out + (size_t)Bc * Hc * Sc * Dc;   // outputs concatenated: (output, attn)

    cudaFuncSetAttribute(attn_fwd, cudaFuncAttributeMaxDynamicSharedMemorySize, SMEM_BYTES);

    dim3 g1(Sc / BM, BHc);
    attn_fwd<<<g1, 256, SMEM_BYTES>>>(q, k, v, out, attn);

    softmax_fin<<<BHc * Sc, 256>>>(attn);
}

// round 9
// speedup vs baseline: 1.0155x; 1.0155x over previous
#include <cuda_runtime.h>

// Problem constants (B,H,S,DK) = (4,16,2048,128)
#define Bc   4
#define Hc   16
#define Sc   2048
#define Dc   128
#define BHc  (Bc*Hc)
#define BM   64
#define BN   64
#define SCALE 0.08838834764831845f   // 1/sqrt(128)

// Per-row softmax stats scratch (allocation-free: __device__ globals)
__device__ float g_m[BHc * Sc];
__device__ float g_l[BHc * Sc];

typedef unsigned long long u64;

__device__ __forceinline__ u64 pk2(float lo, float hi) {
    u64 r; asm("mov.b64 %0, {%1, %2};" : "=l"(r) : "f"(lo), "f"(hi)); return r;
}
__device__ __forceinline__ u64 dup2(float x) { return pk2(x, x); }
__device__ __forceinline__ void upk2(u64 v, float& lo, float& hi) {
    asm("mov.b64 {%0, %1}, %2;" : "=f"(lo), "=f"(hi) : "l"(v));
}
__device__ __forceinline__ u64 fma2(u64 a, u64 b, u64 c) {
    u64 d; asm("fma.rn.f32x2 %0, %1, %2, %3;" : "=l"(d) : "l"(a), "l"(b), "l"(c)); return d;
}
__device__ __forceinline__ u64 mul2(u64 a, u64 b) {
    u64 d; asm("mul.rn.f32x2 %0, %1, %2;" : "=l"(d) : "l"(a), "l"(b)); return d;
}

// Dynamic smem layout (floats):
//  Qs: [128][64]  (transposed: [d][row])        8192
//  Ks: [128][64]  (transposed: [d][col])        8192
//  Vs: [64][128]  ([j][d], row-major)           8192
//  Ps: [64][68]   ([row][j], padded)            4352
#define SMEM_FLOATS (8192 + 8192 + 8192 + 64*68)
#define SMEM_BYTES  (SMEM_FLOATS * 4)

__global__ __launch_bounds__(256, 2)
void attn_fwd(const float* __restrict__ q,
              const float* __restrict__ k,
              const float* __restrict__ v,
              float* __restrict__ out,
              float* __restrict__ attn)
{
    extern __shared__ float sm[];
    float* Qs = sm;                 // 128 x 64
    float* Ks = sm + 8192;          // 128 x 64
    float* Vs = sm + 16384;         // 64 x 128
    float* Ps = sm + 24576;         // 64 x 68

    const int tid = threadIdx.x;
    const int tx  = tid & 15;       // column group (4 cols each)
    const int ty  = tid >> 4;       // row group (4 rows each)
    const int ty4 = ty * 4;
    const int tx4 = tx * 4;
    const int bh  = blockIdx.y;
    const int qt  = (gridDim.x - 1) - blockIdx.x;   // heavy tiles scheduled first
    const int i0  = qt * BM;
    const size_t qkv_bh = (size_t)bh * Sc * Dc;

    // ---- Load Q tile transposed (Qs[d][row]); conflict-free smem stores ----
    for (int t = tid; t < BM * 32; t += 256) {
        int row = t & 63;
        int d4  = t >> 6;
        float4 val = *(const float4*)(q + qkv_bh + (size_t)(i0 + row) * Dc + d4 * 4);
        Qs[(d4*4 + 0) * 64 + row] = val.x;
        Qs[(d4*4 + 1) * 64 + row] = val.y;
        Qs[(d4*4 + 2) * 64 + row] = val.z;
        Qs[(d4*4 + 3) * 64 + row] = val.w;
    }
    __syncthreads();

    float m[4] = {-1e30f, -1e30f, -1e30f, -1e30f};
    float l[4] = {0.f, 0.f, 0.f, 0.f};
    u64 O2[8][2];                   // O2[co][p]: packed rows (2p,2p+1), col = tx*8+co
    #pragma unroll
    for (int co = 0; co < 8; co++) { O2[co][0] = 0ull; O2[co][1] = 0ull; }

    for (int jt = 0; jt <= qt; jt++) {
        const int j0 = jt * BN;

        // ---- Load K tile transposed + V tile straight ----
        for (int t = tid; t < BN * 32; t += 256) {
            int row = t & 63;
            int d4  = t >> 6;
            float4 val = *(const float4*)(k + qkv_bh + (size_t)(j0 + row) * Dc + d4 * 4);
            Ks[(d4*4 + 0) * 64 + row] = val.x;
            Ks[(d4*4 + 1) * 64 + row] = val.y;
            Ks[(d4*4 + 2) * 64 + row] = val.z;
            Ks[(d4*4 + 3) * 64 + row] = val.w;
        }
        for (int t = tid; t < BN * 32; t += 256) {
            int row = t >> 5;
            int d4  = t & 31;
            *(float4*)(Vs + row * 128 + d4 * 4) =
                *(const float4*)(v + qkv_bh + (size_t)(j0 + row) * Dc + d4 * 4);
        }
        __syncthreads();

        // ---- S = Q @ K^T (64x64x128), f32x2-packed accumulators ----
        u64 acc[4][2];
        #pragma unroll
        for (int c = 0; c < 4; c++) { acc[c][0] = 0ull; acc[c][1] = 0ull; }

        #pragma unroll 8
        for (int kk = 0; kk < 128; kk++) {
            ulonglong2 a = *(const ulonglong2*)(Qs + kk * 64 + ty4); // rows (0,1),(2,3)
            float4 bv = *(const float4*)(Ks + kk * 64 + tx4);
            float bb[4] = {bv.x, bv.y, bv.z, bv.w};
            #pragma unroll
            for (int c = 0; c < 4; c++) {
                u64 b = dup2(bb[c]);
                acc[c][0] = fma2(a.x, b, acc[c][0]);
                acc[c][1] = fma2(a.y, b, acc[c][1]);
            }
        }

        float s[4][4];  // s[c][r]
        #pragma unroll
        for (int c = 0; c < 4; c++) {
            float r0, r1, r2, r3;
            upk2(acc[c][0], r0, r1);
            upk2(acc[c][1], r2, r3);
            s[c][0] = r0 * SCALE; s[c][1] = r1 * SCALE;
            s[c][2] = r2 * SCALE; s[c][3] = r3 * SCALE;
        }

        // ---- causal mask on the diagonal tile ----
        if (jt == qt) {
            #pragma unroll
            for (int c = 0; c < 4; c++) {
                int j = j0 + tx4 + c;
                #pragma unroll
                for (int r = 0; r < 4; r++) {
                    int i = i0 + ty4 + r;
                    if (j > i) s[c][r] = -1e30f;
                }
            }
        }

        // ---- write RAW scaled scores into attn buffer (scratch for pass 2) ----
        #pragma unroll
        for (int r = 0; r < 4; r++) {
            *(float4*)(attn + ((size_t)bh * Sc + (size_t)(i0 + ty4 + r)) * Sc + j0 + tx4)
                = make_float4(s[0][r], s[1][r], s[2][r], s[3][r]);
        }

        // ---- online softmax (per row, 16-lane butterfly within warp halves) ----
        float corr[4];
        #pragma unroll
        for (int r = 0; r < 4; r++) {
            float tmax = fmaxf(fmaxf(s[0][r], s[1][r]), fmaxf(s[2][r], s[3][r]));
            #pragma unroll
            for (int off = 1; off < 16; off <<= 1)
                tmax = fmaxf(tmax, __shfl_xor_sync(0xffffffffu, tmax, off));
            float nm = fmaxf(m[r], tmax);
            corr[r]  = __expf(m[r] - nm);
            m[r]     = nm;
            float p0 = __expf(s[0][r] - nm);
            float p1 = __expf(s[1][r] - nm);
            float p2 = __expf(s[2][r] - nm);
            float p3 = __expf(s[3][r] - nm);
            float rs = (p0 + p1) + (p2 + p3);
            #pragma unroll
            for (int off = 1; off < 16; off <<= 1)
                rs += __shfl_xor_sync(0xffffffffu, rs, off);
            l[r] = l[r] * corr[r] + rs;
            *(float4*)(Ps + (ty4 + r) * 68 + tx4) = make_float4(p0, p1, p2, p3);
        }

        // ---- rescale O accumulator ----
        {
            u64 c01 = pk2(corr[0], corr[1]);
            u64 c23 = pk2(corr[2], corr[3]);
            #pragma unroll
            for (int co = 0; co < 8; co++) {
                O2[co][0] = mul2(O2[co][0], c01);
                O2[co][1] = mul2(O2[co][1], c23);
            }
        }
        __syncthreads();   // Ps complete before PV reads it

        // ---- O += P @ V (64x128x64) ----
        #pragma unroll 4
        for (int j = 0; j < 64; j++) {
            float a0 = Ps[(ty4 + 0) * 68 + j];
            float a1 = Ps[(ty4 + 1) * 68 + j];
            float a2 = Ps[(ty4 + 2) * 68 + j];
            float a3 = Ps[(ty4 + 3) * 68 + j];
            u64 a01 = pk2(a0, a1);
            u64 a23 = pk2(a2, a3);
            float4 v0 = *(const float4*)(Vs + j * 128 + tx * 8);
            float4 v1 = *(const float4*)(Vs + j * 128 + tx * 8 + 4);
            float bvals[8] = {v0.x, v0.y, v0.z, v0.w, v1.x, v1.y, v1.z, v1.w};
            #pragma unroll
            for (int co = 0; co < 8; co++) {
                u64 b = dup2(bvals[co]);
                O2[co][0] = fma2(a01, b, O2[co][0]);
                O2[co][1] = fma2(a23, b, O2[co][1]);
            }
        }
        __syncthreads();   // safe to overwrite Ks/Vs/Ps next iteration
    }

    // ---- epilogue: O / l, store m & l ----
    float invl[4];
    #pragma unroll
    for (int r = 0; r < 4; r++) invl[r] = 1.0f / l[r];

    float o[8][4];
    #pragma unroll
    for (int co = 0; co < 8; co++) {
        upk2(O2[co][0], o[co][0], o[co][1]);
        upk2(O2[co][1], o[co][2], o[co][3]);
    }
    #pragma unroll
    for (int r = 0; r < 4; r++) {
        float4 w0 = make_float4(o[0][r]*invl[r], o[1][r]*invl[r],
                                o[2][r]*invl[r], o[3][r]*invl[r]);
        float4 w1 = make_float4(o[4][r]*invl[r], o[5][r]*invl[r],
                                o[6][r]*invl[r], o[7][r]*invl[r]);
        size_t ob = qkv_bh + (size_t)(i0 + ty4 + r) * Dc + tx * 8;
        *(float4*)(out + ob)     = w0;
        *(float4*)(out + ob + 4) = w1;
    }
    if (tx == 0) {
        #pragma unroll
        for (int r = 0; r < 4; r++) {
            int row = bh * Sc + i0 + ty4 + r;
            g_m[row] = m[r];
            g_l[row] = l[r];
        }
    }
}

// Pass 2: finalize attn in place: p = exp(s - m)/l for j<=i, 0 otherwise.
__global__ __launch_bounds__(256)
void softmax_fin(float* __restrict__ attn)
{
    const int row = blockIdx.x;          // bh*S + i
    const int i   = row & (Sc - 1);
    const float mm  = g_m[row];
    const float inv = 1.0f / g_l[row];
    float* rp = attn + (size_t)row * Sc;

    for (int c4 = threadIdx.x; c4 < Sc / 4; c4 += blockDim.x) {
        int j0 = c4 << 2;
        float4 o;
        if (j0 + 3 <= i) {
            float4 sv = *(const float4*)(rp + j0);
            o.x = __expf(sv.x - mm) * inv;
            o.y = __expf(sv.y - mm) * inv;
            o.z = __expf(sv.z - mm) * inv;
            o.w = __expf(sv.w - mm) * inv;
        } else if (j0 > i) {
            o = make_float4(0.f, 0.f, 0.f, 0.f);
        } else {
            float t[4];
            #pragma unroll
            for (int u = 0; u < 4; u++) {
                int j = j0 + u;
                t[u] = (j <= i) ? __expf(rp[j] - mm) * inv : 0.f;
            }
            o = make_float4(t[0], t[1], t[2], t[3]);
        }
        *(float4*)(rp + j0) = o;
    }
}

extern "C" void kernel_launch(void* const* d_in, const int* in_sizes, int n_in,
                              void* d_out, int out_size)
{
    const float* q = (const float*)d_in[0];
    const float* k = (const float*)d_in[1];
    const float* v = (const float*)d_in[2];
    // d_in[3] is the causal mask; causality is applied analytically (j<=i).

    float* out  = (float*)d_out;
    float* attn = out + (size_t)Bc * Hc * Sc * Dc;   // outputs concatenated: (output, attn)

    cudaFuncSetAttribute(attn_fwd, cudaFuncAttributeMaxDynamicSharedMemorySize, SMEM_BYTES);

    dim3 g1(Sc / BM, BHc);
    attn_fwd<<<g1, 256, SMEM_BYTES>>>(q, k, v, out, attn);

    softmax_fin<<<BHc * Sc, 256>>>(attn);
}